// round 10
// baseline (speedup 1.0000x reference)
#include <cuda_runtime.h>
#include <math.h>

#define Nn 64
#define Cc 256
#define Tt 64
#define Vv 25
#define HID 16
#define NG 5
#define TV (Tt*Vv)     // 1600
#define TV4 (TV/4)     // 400
#define NCHUNK 4
#define NPC (Nn/NCHUNK)     // 16 n per chunk
#define CHSL (NPC*Cc)       // 4096 slices per chunk

// Scratch (allowed: __device__ globals, no allocation)
__device__ float g_avg[Nn*Cc];
__device__ float g_max[Nn*Cc];
__device__ float g_gates[Nn*NG*Cc];

// Gather tables in __device__ global (L1 gather; NOT __constant__ — divergent
// indexed constant access serializes).
__device__ int d_perm[Vv] = {0,1,2,3,20, 8,9,10,11,23,24, 16,17,18,19, 4,5,6,7,21,22, 12,13,14,15};
__device__ int d_grp [Vv] = {0,0,0,0,0,  1,1,1,1,1,1,     2,2,2,2,     3,3,3,3,3,3,   4,4,4,4};

// ---------------------------------------------------------------------------
// Combined kernel A: odd blocks run K1 (torso reduce) for chunk `ck`,
// even blocks run K3 (gated permuted write) for chunk `ck-1`.
// Interleaving odd/even makes DRAM reads (K1) overlap DRAM writes (K3),
// and keeps the K3 chunk's x L2-resident (loaded by the PREVIOUS A kernel).
// ---------------------------------------------------------------------------
__global__ void __launch_bounds__(256) k_pair(const float* __restrict__ x,
                                              float* __restrict__ out,
                                              int ck) {
    int pair = blockIdx.x >> 1;          // 0..CHSL-1
    int tid  = threadIdx.x;

    if (blockIdx.x & 1) {
        // ---------------- K1: reduce slice of chunk ck ----------------
        if (ck >= NCHUNK) return;
        int nc = ck * CHSL + pair;
        float s = 0.f, m = -__builtin_huge_valf();
        if (tid < 200) {
            int e  = 4 * tid;
            int t0 = e / 25;
            int v  = e - t0 * 25;        // phase constant across the 2 loads (stride 800 ≡ 0 mod 25)
            int v1 = (v+1) >= 25 ? v+1-25 : v+1;
            int v2 = (v+2) >= 25 ? v+2-25 : v+2;
            int v3 = (v+3) >= 25 ? v+3-25 : v+3;
            bool t_0 = (v  < 4) | (v  == 20);
            bool t_1 = (v1 < 4) | (v1 == 20);
            bool t_2 = (v2 < 4) | (v2 == 20);
            bool t_3 = (v3 < 4) | (v3 == 20);
            const float4* p = reinterpret_cast<const float4*>(x + (size_t)nc * TV) + tid;
            #pragma unroll
            for (int r = 0; r < 2; r++) {
                float4 q = p[r * 200];
                if (t_0) { s += q.x; m = fmaxf(m, q.x); }
                if (t_1) { s += q.y; m = fmaxf(m, q.y); }
                if (t_2) { s += q.z; m = fmaxf(m, q.z); }
                if (t_3) { s += q.w; m = fmaxf(m, q.w); }
            }
        }
        #pragma unroll
        for (int o = 16; o > 0; o >>= 1) {
            s += __shfl_xor_sync(0xFFFFFFFFu, s, o);
            m  = fmaxf(m, __shfl_xor_sync(0xFFFFFFFFu, m, o));
        }
        __shared__ float sh_s[8], sh_m[8];
        int warp = tid >> 5;
        if ((tid & 31) == 0) { sh_s[warp] = s; sh_m[warp] = m; }
        __syncthreads();
        if (tid == 0) {
            float S = 0.f, M = -__builtin_huge_valf();
            #pragma unroll
            for (int w = 0; w < 7; w++) { S += sh_s[w]; M = fmaxf(M, sh_m[w]); }
            g_avg[nc] = S * (1.0f / 320.0f);   // mean over T*5 = 320
            g_max[nc] = M;
        }
    } else {
        // ---------------- K3: apply slice of chunk ck-1 ----------------
        if (ck == 0) return;
        int nc = (ck - 1) * CHSL + pair;
        int n = nc >> 8, c = nc & 255;
        __shared__ float sgv[Vv];
        __shared__ int   spv[Vv];
        if (tid < Vv) {
            sgv[tid] = g_gates[(n*NG + d_grp[tid])*Cc + c];
            spv[tid] = d_perm[tid];
        }
        __syncthreads();

        const float* px  = x + (size_t)nc * TV;
        float4*      po4 = reinterpret_cast<float4*>(out + (size_t)nc * TV);
        #pragma unroll
        for (int r = 0; r < 2; r++) {
            int i4 = tid + r * 256;
            if (i4 < TV4) {
                int e   = 4 * i4;
                int t   = e / 25;
                int vo  = e - t * 25;
                const float* bs = px + t * 25;
                float res[4];
                #pragma unroll
                for (int j = 0; j < 4; j++) {
                    res[j] = __ldg(bs + spv[vo]) * sgv[vo];
                    vo++;
                    if (vo == Vv) { vo = 0; bs += Vv; }
                }
                __stcs(po4 + i4, make_float4(res[0], res[1], res[2], res[3]));
            }
        }
    }
}

// ---------------------------------------------------------------------------
// K2: gates[n,f,c] = sigmoid( mlp_f(avg[n,:]) + mlp_f(max[n,:]) )
// One block per n within the chunk, 256 threads.
// ---------------------------------------------------------------------------
__global__ void __launch_bounds__(256) k_mlp(
        const float* __restrict__ W1s, const float* __restrict__ b1s,
        const float* __restrict__ W2s, const float* __restrict__ b2s,
        int ck) {
    int n   = ck * NPC + blockIdx.x;
    int tid = threadIdx.x;
    __shared__ float sA[Cc], sM[Cc], hs[NG*HID];

    sA[tid] = g_avg[n*Cc + tid];
    sM[tid] = g_max[n*Cc + tid];
    __syncthreads();

    int warp = tid >> 5, lane = tid & 31;
    for (int task = warp; task < NG*HID; task += 8) {
        const float* w1 = W1s + task * Cc;
        float a = 0.f, m = 0.f;
        #pragma unroll
        for (int k = 0; k < 8; k++) {
            float w = w1[lane + 32*k];
            a += sA[lane + 32*k] * w;
            m += sM[lane + 32*k] * w;
        }
        #pragma unroll
        for (int o = 16; o > 0; o >>= 1) {
            a += __shfl_xor_sync(0xFFFFFFFFu, a, o);
            m += __shfl_xor_sync(0xFFFFFFFFu, m, o);
        }
        if (lane == 0) {
            float b = b1s[task];
            hs[task] = fmaxf(a + b, 0.f) + fmaxf(m + b, 0.f);
        }
    }
    __syncthreads();

    int c = tid;
    #pragma unroll
    for (int f = 0; f < NG; f++) {
        const float4* w2 = reinterpret_cast<const float4*>(W2s + ((size_t)(f*Cc + c)) * HID);
        float acc = 2.0f * b2s[f*Cc + c];
        #pragma unroll
        for (int q = 0; q < 4; q++) {
            float4 w = w2[q];
            acc += hs[f*HID + 4*q + 0] * w.x;
            acc += hs[f*HID + 4*q + 1] * w.y;
            acc += hs[f*HID + 4*q + 2] * w.z;
            acc += hs[f*HID + 4*q + 3] * w.w;
        }
        g_gates[(n*NG + f)*Cc + c] = 1.0f / (1.0f + expf(-acc));
    }
}

extern "C" void kernel_launch(void* const* d_in, const int* in_sizes, int n_in,
                              void* d_out, int out_size) {
    const float* x   = (const float*)d_in[0];
    const float* W1s = (const float*)d_in[1];
    const float* b1s = (const float*)d_in[2];
    const float* W2s = (const float*)d_in[3];
    const float* b2s = (const float*)d_in[4];
    float* out = (float*)d_out;

    // Pipeline: A_i = (apply chunk i-1) ∥ (reduce chunk i); B_i = MLP chunk i.
    for (int ck = 0; ck <= NCHUNK; ck++) {
        k_pair<<<2*CHSL, 256>>>(x, out, ck);
        if (ck < NCHUNK)
            k_mlp<<<NPC, 256>>>(W1s, b1s, W2s, b2s, ck);
    }
}

// round 11
// speedup vs baseline: 1.3209x; 1.3209x over previous
#include <cuda_runtime.h>
#include <math.h>

#define Nn 64
#define Cc 256
#define Tt 64
#define Vv 25
#define HID 16
#define NG 5
#define TV (Tt*Vv)     // 1600
#define TV4 (TV/4)     // 400
#define NCHUNK 4
#define NPC (Nn/NCHUNK)     // 16 n per chunk
#define CHSL (NPC*Cc)       // 4096 slices per chunk

// Scratch (allowed: __device__ globals, no allocation)
__device__ float g_avg[Nn*Cc];
__device__ float g_max[Nn*Cc];
__device__ float g_gates[Nn*NG*Cc];

// Gather tables in __device__ global (L1 gather; NOT __constant__ — divergent
// indexed constant access serializes).
__device__ int d_perm[Vv] = {0,1,2,3,20, 8,9,10,11,23,24, 16,17,18,19, 4,5,6,7,21,22, 12,13,14,15};
__device__ int d_grp [Vv] = {0,0,0,0,0,  1,1,1,1,1,1,     2,2,2,2,     3,3,3,3,3,3,   4,4,4,4};

// ---------------------------------------------------------------------------
// Combined kernel A: odd blocks run K1 (torso reduce) for chunk `ck`,
// even blocks run K3 (gated permuted write) for chunk `ck-1`.
// Interleaving overlaps DRAM reads (K1) with writes (K3); the apply chunk's
// x is L2-resident (26 MB, loaded by the previous pair's reduce).
// ---------------------------------------------------------------------------
__global__ void __launch_bounds__(256) k_pair(const float* __restrict__ x,
                                              float* __restrict__ out,
                                              int ck) {
    int pair = blockIdx.x >> 1;          // 0..CHSL-1
    int tid  = threadIdx.x;

    if (blockIdx.x & 1) {
        // ---------------- K1: reduce slice of chunk ck ----------------
        if (ck >= NCHUNK) return;
        int nc = ck * CHSL + pair;
        float s = 0.f, m = -__builtin_huge_valf();
        if (tid < 200) {
            int e  = 4 * tid;
            int t0 = e / 25;
            int v  = e - t0 * 25;        // phase constant across the 2 loads (stride 800 ≡ 0 mod 25)
            int v1 = (v+1) >= 25 ? v+1-25 : v+1;
            int v2 = (v+2) >= 25 ? v+2-25 : v+2;
            int v3 = (v+3) >= 25 ? v+3-25 : v+3;
            bool t_0 = (v  < 4) | (v  == 20);
            bool t_1 = (v1 < 4) | (v1 == 20);
            bool t_2 = (v2 < 4) | (v2 == 20);
            bool t_3 = (v3 < 4) | (v3 == 20);
            const float4* p = reinterpret_cast<const float4*>(x + (size_t)nc * TV) + tid;
            #pragma unroll
            for (int r = 0; r < 2; r++) {
                float4 q = p[r * 200];
                if (t_0) { s += q.x; m = fmaxf(m, q.x); }
                if (t_1) { s += q.y; m = fmaxf(m, q.y); }
                if (t_2) { s += q.z; m = fmaxf(m, q.z); }
                if (t_3) { s += q.w; m = fmaxf(m, q.w); }
            }
        }
        #pragma unroll
        for (int o = 16; o > 0; o >>= 1) {
            s += __shfl_xor_sync(0xFFFFFFFFu, s, o);
            m  = fmaxf(m, __shfl_xor_sync(0xFFFFFFFFu, m, o));
        }
        __shared__ float sh_s[8], sh_m[8];
        int warp = tid >> 5;
        if ((tid & 31) == 0) { sh_s[warp] = s; sh_m[warp] = m; }
        __syncthreads();
        if (tid == 0) {
            float S = 0.f, M = -__builtin_huge_valf();
            #pragma unroll
            for (int w = 0; w < 7; w++) { S += sh_s[w]; M = fmaxf(M, sh_m[w]); }  // warps 0..6 cover the 200 active threads
            g_avg[nc] = S * (1.0f / 320.0f);   // mean over T*5 = 320
            g_max[nc] = M;
        }
    } else {
        // ---------------- K3: apply slice of chunk ck-1 ----------------
        if (ck == 0) return;
        int nc = (ck - 1) * CHSL + pair;
        int n = nc >> 8, c = nc & 255;
        __shared__ float sgv[Vv];
        __shared__ int   spv[Vv];
        if (tid < Vv) {
            sgv[tid] = g_gates[(n*NG + d_grp[tid])*Cc + c];
            spv[tid] = d_perm[tid];
        }
        __syncthreads();

        const float* px  = x + (size_t)nc * TV;
        float4*      po4 = reinterpret_cast<float4*>(out + (size_t)nc * TV);
        #pragma unroll
        for (int r = 0; r < 2; r++) {
            int i4 = tid + r * 256;
            if (i4 < TV4) {
                int e   = 4 * i4;
                int t   = e / 25;
                int vo  = e - t * 25;
                const float* bs = px + t * 25;
                float res[4];
                #pragma unroll
                for (int j = 0; j < 4; j++) {
                    res[j] = __ldg(bs + spv[vo]) * sgv[vo];
                    vo++;
                    if (vo == Vv) { vo = 0; bs += Vv; }
                }
                __stcs(po4 + i4, make_float4(res[0], res[1], res[2], res[3]));
            }
        }
    }
}

// ---------------------------------------------------------------------------
// K2: gates[n,f,c] = sigmoid( mlp_f(avg[n,:]) + mlp_f(max[n,:]) )
// ONE BLOCK PER (n,f) — grid NPC*NG = 80 per chunk — so DRAM-latency chains
// on cold weights are overlapped 5x more than the grid-16 version, and each
// warp owns only 2 hidden units (short dependency chain).
// ---------------------------------------------------------------------------
__global__ void __launch_bounds__(256) k_mlp(
        const float* __restrict__ W1s, const float* __restrict__ b1s,
        const float* __restrict__ W2s, const float* __restrict__ b2s,
        int ck) {
    int bx  = blockIdx.x;
    int n   = ck * NPC + bx / NG;
    int f   = bx - (bx / NG) * NG;
    int tid = threadIdx.x;
    __shared__ float sA[Cc], sM[Cc], hs[HID];

    sA[tid] = g_avg[n*Cc + tid];
    sM[tid] = g_max[n*Cc + tid];
    __syncthreads();

    int warp = tid >> 5, lane = tid & 31;
    // 16 hidden units, 8 warps -> 2 per warp
    #pragma unroll
    for (int u = 0; u < 2; u++) {
        int j = warp * 2 + u;
        const float* w1 = W1s + (f*HID + j) * Cc;
        float a = 0.f, m = 0.f;
        #pragma unroll
        for (int k = 0; k < 8; k++) {
            float w = w1[lane + 32*k];
            a += sA[lane + 32*k] * w;
            m += sM[lane + 32*k] * w;
        }
        #pragma unroll
        for (int o = 16; o > 0; o >>= 1) {
            a += __shfl_xor_sync(0xFFFFFFFFu, a, o);
            m += __shfl_xor_sync(0xFFFFFFFFu, m, o);
        }
        if (lane == 0) {
            float b = b1s[f*HID + j];
            hs[j] = fmaxf(a + b, 0.f) + fmaxf(m + b, 0.f);
        }
    }
    __syncthreads();

    int c = tid;
    const float4* w2 = reinterpret_cast<const float4*>(W2s + ((size_t)(f*Cc + c)) * HID);
    float acc = 2.0f * b2s[f*Cc + c];
    #pragma unroll
    for (int q = 0; q < 4; q++) {
        float4 w = w2[q];
        acc += hs[4*q + 0] * w.x;
        acc += hs[4*q + 1] * w.y;
        acc += hs[4*q + 2] * w.z;
        acc += hs[4*q + 3] * w.w;
    }
    g_gates[(n*NG + f)*Cc + c] = 1.0f / (1.0f + expf(-acc));
}

extern "C" void kernel_launch(void* const* d_in, const int* in_sizes, int n_in,
                              void* d_out, int out_size) {
    const float* x   = (const float*)d_in[0];
    const float* W1s = (const float*)d_in[1];
    const float* b1s = (const float*)d_in[2];
    const float* W2s = (const float*)d_in[3];
    const float* b2s = (const float*)d_in[4];
    float* out = (float*)d_out;

    // Pipeline: A_i = (apply chunk i-1) ∥ (reduce chunk i); B_i = MLP chunk i.
    for (int ck = 0; ck <= NCHUNK; ck++) {
        k_pair<<<2*CHSL, 256>>>(x, out, ck);
        if (ck < NCHUNK)
            k_mlp<<<NPC*NG, 256>>>(W1s, b1s, W2s, b2s, ck);
    }
}